// round 14
// baseline (speedup 1.0000x reference)
#include <cuda_runtime.h>
#include <cuda_bf16.h>
#include <cuda_fp16.h>
#include <cstdint>

#define NF 256
#define NT 64
#define NDEP 6
#define NTD 384
#define NLEAF 64
#define NU 128
#define NSAMP 16384
#define TS 128
#define NBLK (NSAMP / TS)
#define NTHR 512

// ---- smem map (bytes) ----
// X resident fp16 tile (4 chunks of 16KB): [0, 65536)
// sp (fp32 p-values / epilogue staging):   [65536, 163840)
// CBUF (phase-C B frags, 4 wn x 2 bufs x 4KB): [163840, 196608)
#define SP_FLOAT 16384
#define CBUF_BYTE 163840
#define SMEM_BYTES 196608

__device__ float2 g_thrT[NTD];            // {threshold, exp(-logT)} per td
// R pre-packed in m16n8k16 B-fragment order (verified R8), scaled by 1/64:
__device__ uint4 g_rf[NT * 4 * 8 * 32];
// sel fp16 B-fragments: j = ((((h*4+kc)*4+wn)*6+nt)*4+kk)*32+lane ; uint2 = {reg0, reg1}
__device__ uint2 g_sf[2 * 4 * 4 * 6 * 4 * 32];

__device__ __forceinline__ uint32_t cvt2h(float lo, float hi) {
    uint32_t r; asm("cvt.rn.f16x2.f32 %0, %1, %2;" : "=r"(r) : "f"(hi), "f"(lo)); return r;
}
__device__ __forceinline__ uint32_t smem_u32(const void* p) {
    uint32_t a;
    asm("{ .reg .u64 t; cvta.to.shared.u64 t, %1; cvt.u32.u64 %0, t; }" : "=r"(a) : "l"(p));
    return a;
}
__device__ __forceinline__ void ldsm4(uint32_t* r, uint32_t addr) {
    asm volatile("ldmatrix.sync.aligned.m8n8.x4.shared.b16 {%0,%1,%2,%3}, [%4];"
                 : "=r"(r[0]), "=r"(r[1]), "=r"(r[2]), "=r"(r[3]) : "r"(addr));
}
__device__ __forceinline__ uint4 lds128(uint32_t a) {
    uint4 v;
    asm volatile("ld.shared.v4.u32 {%0,%1,%2,%3}, [%4];"
                 : "=r"(v.x), "=r"(v.y), "=r"(v.z), "=r"(v.w) : "r"(a));
    return v;
}
__device__ __forceinline__ void cp16(uint32_t dst, const void* src) {
    asm volatile("cp.async.cg.shared.global [%0], [%1], 16;" :: "r"(dst), "l"(src));
}
__device__ __forceinline__ void mma16816(float* d, const uint32_t* a, uint32_t b0, uint32_t b1) {
    asm volatile(
        "mma.sync.aligned.m16n8k16.row.col.f32.f16.f16.f32 "
        "{%0,%1,%2,%3}, {%4,%5,%6,%7}, {%8,%9}, {%0,%1,%2,%3};"
        : "+f"(d[0]), "+f"(d[1]), "+f"(d[2]), "+f"(d[3])
        : "r"(a[0]), "r"(a[1]), "r"(a[2]), "r"(a[3]), "r"(b0), "r"(b1));
}

// ---------------- prep (merged): softmax+sel frags | resp frags + thr/invT ----------------
__global__ void prep_all(const float* __restrict__ fl, const float* __restrict__ resp,
                         const float* __restrict__ th, const float* __restrict__ lt) {
    const int tid = threadIdx.x;
    if (blockIdx.x < NTD) {
        __shared__ float red[8];
        __shared__ float sval[NF];
        const int td = blockIdx.x;

        float v = fl[tid * NTD + td];
        float m = v;
        #pragma unroll
        for (int o = 16; o; o >>= 1) m = fmaxf(m, __shfl_xor_sync(0xffffffffu, m, o));
        if ((tid & 31) == 0) red[tid >> 5] = m;
        __syncthreads();
        float bm = red[0];
        #pragma unroll
        for (int k = 1; k < 8; k++) bm = fmaxf(bm, red[k]);
        __syncthreads();
        float e = __expf(v - bm);
        float s = e;
        #pragma unroll
        for (int o = 16; o; o >>= 1) s += __shfl_xor_sync(0xffffffffu, s, o);
        if ((tid & 31) == 0) red[tid >> 5] = s;
        __syncthreads();
        float bs = 0.0f;
        #pragma unroll
        for (int k = 0; k < 8; k++) bs += red[k];
        sval[tid] = e / bs;
        __syncthreads();

        if (tid < 64) {
            int kc = tid >> 4, kk = (tid >> 2) & 3, fq = tid & 3;
            int h = td / 192, r = td % 192;
            int wn = r / 48, r2 = r % 48;
            int nt = r2 / 8, lr = r2 % 8;
            int lane = lr * 4 + fq;
            int f0 = kc * 64 + kk * 16 + fq * 2;
            uint32_t h0 = cvt2h(sval[f0],     sval[f0 + 1]);
            uint32_t h1 = cvt2h(sval[f0 + 8], sval[f0 + 9]);
            int j = ((((h * 4 + kc) * 4 + wn) * 6 + nt) * 4 + kk) * 32 + lane;
            g_sf[j] = make_uint2(h0, h1);
        }
    } else {
        int i = (blockIdx.x - NTD) * 256 + tid;    // < 262144 uint32
        if (i < NTD) g_thrT[i] = make_float2(th[i], __expf(-lt[i]));
        int fi   = i & 3;
        int lane = (i >> 2) & 31;
        int q    = (i >> 7) & 7;
        int wn   = (i >> 10) & 3;
        int t    = i >> 12;
        int m    = q * 4 + fi;
        int slot = m >> 1, reg = m & 1;
        int kk   = slot >> 2, nt = slot & 3;
        int n    = wn * 32 + nt * 8 + (lane >> 2);
        int k    = kk * 16 + (lane & 3) * 2 + reg * 8;
        const float* rb = resp + t * (NU * NLEAF) + n * NLEAF + k;
        const float sc = 1.0f / 64.0f;
        ((uint32_t*)g_rf)[i] = cvt2h(rb[0] * sc, rb[1] * sc);
    }
}

// ---------------- main fused kernel: 512 threads, 4x4 warp grid ----------------
__global__ __launch_bounds__(NTHR, 1) void odt_main(
    const float* __restrict__ x, float* __restrict__ out)
{
    extern __shared__ float smem[];
    char* smemc = (char*)smem;
    float* sp = smem + SP_FLOAT;

    const int tid = threadIdx.x;
    const int wid = tid >> 5;
    const int lid = tid & 31;
    const int s0  = blockIdx.x * TS;
    const uint32_t smem_base = smem_u32(smem);

    // 4x4 warp tiling (both phases): warp (wm, wn)
    const int wm = wid >> 2, wn = wid & 3;
    const uint32_t swz = (lid & 7) * 16;
    uint32_t xa[4];
    #pragma unroll
    for (int kk = 0; kk < 4; ++kk)
        xa[kk] = ((uint32_t)(kk * 32) + ((lid >> 4) * 16)) ^ swz;
    const uint32_t aRowOff = (wm * 32 + (lid & 15)) * 128;

    // cp.async prefetch of tree gt's B-fragment slice into CBUF buffer p
    // (cooperative across the 4 warps sharing wn; each warp copies 2x16B per lane)
    const uint32_t cbuf_wn = smem_base + CBUF_BYTE + wn * 8192;
    const int pidx1 = wm * 64 + lid, pidx2 = pidx1 + 32;
    #define PREFETCH_TREE(gt, p) do {                                        \
        const char* _src = (const char*)(g_rf + (size_t)((gt) * 4 + wn) * 256); \
        uint32_t _dst = cbuf_wn + (p) * 4096;                                \
        cp16(_dst + pidx1 * 16, _src + pidx1 * 16);                          \
        cp16(_dst + pidx2 * 16, _src + pidx2 * 16);                          \
        asm volatile("cp.async.commit_group;" ::: "memory");                 \
    } while (0)

    // prologue: prefetch tree 0 (hidden under x-tile load + phase B)
    PREFETCH_TREE(0, 0);

    // ---- load x ONCE: [128 s][256 f] fp32 -> fp16 swizzled resident tile ----
    #pragma unroll
    for (int it = 0; it < 16; ++it) {
        int idx = tid + it * NTHR;         // 8192 float4
        int chunk = idx >> 11;
        int r = idx & 2047;
        int row = r >> 4, c4 = r & 15;
        float4 v = *(const float4*)(x + (s0 + row) * NF + chunk * 64 + c4 * 4);
        char* dh = smemc + chunk * 16384;
        int base = row * 128;
        int sz = (row & 7) * 16;
        *(uint32_t*)(dh + base + ((c4 * 8) ^ sz))     = cvt2h(v.x, v.y);
        *(uint32_t*)(dh + base + ((c4 * 8 + 4) ^ sz)) = cvt2h(v.z, v.w);
    }
    __syncthreads();

    float acc[2][4][4];                    // phase C accumulators (persist)
    #pragma unroll
    for (int m = 0; m < 2; m++)
        #pragma unroll
        for (int i = 0; i < 4; i++)
            #pragma unroll
            for (int j = 0; j < 4; j++) acc[m][i][j] = 0.0f;

    for (int half = 0; half < 2; ++half) {
        // ---------------- Phase B: fv via single-pass fp16 HMMA (no syncs) ----------------
        float accB[2][6][4];
        #pragma unroll
        for (int m = 0; m < 2; m++)
            #pragma unroll
            for (int i = 0; i < 6; i++)
                #pragma unroll
                for (int j = 0; j < 4; j++) accB[m][i][j] = 0.0f;

        for (int kc = 0; kc < 4; ++kc) {
            const uint32_t xhb = smem_base + kc * 16384;
            const uint2* bp = g_sf + ((size_t)(((half * 4 + kc) * 4 + wn) * 6) * 4) * 32 + lid;
            #pragma unroll
            for (int kk = 0; kk < 4; ++kk) {
                uint2 bq[6];
                #pragma unroll
                for (int nt = 0; nt < 6; ++nt) bq[nt] = bp[(nt * 4 + kk) * 32];
                #pragma unroll
                for (int mt = 0; mt < 2; ++mt) {
                    uint32_t ah[4];
                    ldsm4(ah, xhb + aRowOff + mt * 2048 + xa[kk]);
                    #pragma unroll
                    for (int nt = 0; nt < 6; ++nt)
                        mma16816(accB[mt][nt], ah, bq[nt].x, bq[nt].y);
                }
            }
        }

        __syncthreads();   // prev phase C done reading sp before overwrite
        // sigmoid((fv - thr) * invT) -> sp[td_local][row]
        #pragma unroll
        for (int nt = 0; nt < 6; ++nt) {
            int c0 = wn * 48 + nt * 8 + (lid & 3) * 2;     // td within half
            float4 tt = *(const float4*)&g_thrT[half * 192 + c0];
            #pragma unroll
            for (int mt = 0; mt < 2; ++mt) {
                #pragma unroll
                for (int rr = 0; rr < 2; ++rr) {
                    int row = wm * 32 + mt * 16 + (lid >> 2) + rr * 8;
                    float t0 = (accB[mt][nt][rr * 2]     - tt.x) * tt.y;
                    float t1 = (accB[mt][nt][rr * 2 + 1] - tt.z) * tt.w;
                    sp[c0 * 128 + row]       = __fdividef(1.0f, 1.0f + __expf(-t0));
                    sp[(c0 + 1) * 128 + row] = __fdividef(1.0f, 1.0f + __expf(-t1));
                }
            }
        }
        __syncthreads();   // sp complete; phase C reads it

        // ---------------- Phase C: fp16 HMMA with cp.async double-buffered B ----------------
        for (int tt = 0; tt < 32; ++tt) {
            const int gt = half * 32 + tt;
            const int p = gt & 1;

            // tree gt's B data ready + all 4 wn-group warps done with buffer p^1
            asm volatile("cp.async.wait_group 0;" ::: "memory");
            asm volatile("bar.sync %0, 128;" :: "r"(wn + 1) : "memory");
            if (gt < 63) PREFETCH_TREE(gt + 1, p ^ 1);

            const uint32_t cbase = cbuf_wn + p * 4096 + lid * 16;
            const float* pbase = sp + tt * 6 * 128;

            #pragma unroll
            for (int mt = 0; mt < 2; ++mt) {
                float wlo0[2], wlo1[2], m8[2][8];
                #pragma unroll
                for (int rr = 0; rr < 2; ++rr) {
                    const float* pb = pbase + wm * 32 + mt * 16 + (lid >> 2) + rr * 8;
                    float p0 = pb[0],   p1 = pb[128], p2 = pb[256];
                    float p3 = pb[384], p4 = pb[512], p5 = pb[640];
                    float a0 = 1.f - p0, a1 = 1.f - p1, a2 = 1.f - p2;
                    float a3 = 1.f - p3, a4 = 1.f - p4, a5 = 1.f - p5;
                    float f1 = (lid & 1) ? p1 : a1;
                    float f2 = (lid & 2) ? p2 : a2;
                    float f12 = f1 * f2;
                    wlo0[rr] = f12 * a0;
                    wlo1[rr] = f12 * p0;
                    float g0 = a3 * a4, g1 = p3 * a4, g2 = a3 * p4, g3 = p3 * p4;
                    m8[rr][0] = g0 * a5; m8[rr][1] = g1 * a5;
                    m8[rr][2] = g2 * a5; m8[rr][3] = g3 * a5;
                    m8[rr][4] = g0 * p5; m8[rr][5] = g1 * p5;
                    m8[rr][6] = g2 * p5; m8[rr][7] = g3 * p5;
                }
                #pragma unroll
                for (int kk = 0; kk < 4; ++kk) {
                    uint4 b0 = lds128(cbase + (2 * kk) * 512);
                    uint4 b1 = lds128(cbase + (2 * kk + 1) * 512);
                    uint32_t a[4];
                    a[0] = cvt2h(wlo0[0] * m8[0][2*kk],     wlo1[0] * m8[0][2*kk]);
                    a[1] = cvt2h(wlo0[1] * m8[1][2*kk],     wlo1[1] * m8[1][2*kk]);
                    a[2] = cvt2h(wlo0[0] * m8[0][2*kk + 1], wlo1[0] * m8[0][2*kk + 1]);
                    a[3] = cvt2h(wlo0[1] * m8[1][2*kk + 1], wlo1[1] * m8[1][2*kk + 1]);
                    mma16816(acc[mt][0], a, b0.x, b0.y);
                    mma16816(acc[mt][1], a, b0.z, b0.w);
                    mma16816(acc[mt][2], a, b1.x, b1.y);
                    mma16816(acc[mt][3], a, b1.z, b1.w);
                }
            }
        }
    }

    // ---------------- epilogue: frags -> smem stage -> coalesced global ----------------
    __syncthreads();
    {
        #pragma unroll
        for (int mt = 0; mt < 2; ++mt) {
            int r0 = wm * 32 + mt * 16 + (lid >> 2);
            #pragma unroll
            for (int n8 = 0; n8 < 4; ++n8) {
                int n = wn * 32 + n8 * 8 + (lid & 3) * 2;
                sp[r0 * 132 + n]           = acc[mt][n8][0];
                sp[r0 * 132 + n + 1]       = acc[mt][n8][1];
                sp[(r0 + 8) * 132 + n]     = acc[mt][n8][2];
                sp[(r0 + 8) * 132 + n + 1] = acc[mt][n8][3];
            }
        }
    }
    __syncthreads();

    #pragma unroll
    for (int it = 0; it < 8; ++it) {
        int idx = tid + it * NTHR;
        int s = idx >> 5, u4 = idx & 31;
        float4 v = *(const float4*)(sp + s * 132 + u4 * 4);
        *(float4*)(out + (s0 + s) * NU + u4 * 4) = v;
    }
}

extern "C" void kernel_launch(void* const* d_in, const int* in_sizes, int n_in,
                              void* d_out, int out_size) {
    const float* x  = (const float*)d_in[0];  // [16,1024,256]
    const float* fl = (const float*)d_in[1];  // [256,64,6]
    const float* th = (const float*)d_in[2];  // [64,6]
    const float* lt = (const float*)d_in[3];  // [64,6]
    const float* rs = (const float*)d_in[4];  // [64,128,64]
    float* out      = (float*)d_out;          // [16,1024,128]

    cudaFuncSetAttribute(odt_main, cudaFuncAttributeMaxDynamicSharedMemorySize, SMEM_BYTES);

    prep_all<<<NTD + 1024, 256>>>(fl, rs, th, lt);
    odt_main<<<NBLK, NTHR, SMEM_BYTES>>>(x, out);
}

// round 16
// speedup vs baseline: 1.1223x; 1.1223x over previous
#include <cuda_runtime.h>
#include <cuda_bf16.h>
#include <cuda_fp16.h>
#include <cstdint>

#define NF 256
#define NT 64
#define NDEP 6
#define NTD 384
#define NLEAF 64
#define NU 128
#define NSAMP 16384
#define TS 128
#define NBLK (NSAMP / TS)
#define NTHR 512

// ---- smem map (bytes) ----
// X resident fp16 tile (4 chunks of 16KB): [0, 65536)
// sp (fp32 p-values / epilogue staging):   [65536, 163840)
#define SP_FLOAT 16384
#define SMEM_BYTES 163840

__device__ float2 g_thrT[NTD];            // {threshold, exp(-logT)} per td
// R pre-packed in m16n8k16 B-fragment order (verified R8), scaled by 1/64:
__device__ uint4 g_rf[NT * 4 * 8 * 32];
// sel fp16 B-fragments: j = ((((h*4+kc)*4+wn)*6+nt)*4+kk)*32+lane ; uint2 = {reg0, reg1}
__device__ uint2 g_sf[2 * 4 * 4 * 6 * 4 * 32];

__device__ __forceinline__ uint32_t cvt2h(float lo, float hi) {
    uint32_t r; asm("cvt.rn.f16x2.f32 %0, %1, %2;" : "=r"(r) : "f"(hi), "f"(lo)); return r;
}
__device__ __forceinline__ uint32_t hmul2(uint32_t a, uint32_t b) {
    uint32_t r; asm("mul.rn.f16x2 %0, %1, %2;" : "=r"(r) : "r"(a), "r"(b)); return r;
}
__device__ __forceinline__ uint32_t smem_u32(const void* p) {
    uint32_t a;
    asm("{ .reg .u64 t; cvta.to.shared.u64 t, %1; cvt.u32.u64 %0, t; }" : "=r"(a) : "l"(p));
    return a;
}
__device__ __forceinline__ void ldsm4(uint32_t* r, uint32_t addr) {
    asm volatile("ldmatrix.sync.aligned.m8n8.x4.shared.b16 {%0,%1,%2,%3}, [%4];"
                 : "=r"(r[0]), "=r"(r[1]), "=r"(r[2]), "=r"(r[3]) : "r"(addr));
}
__device__ __forceinline__ void mma16816(float* d, const uint32_t* a, uint32_t b0, uint32_t b1) {
    asm volatile(
        "mma.sync.aligned.m16n8k16.row.col.f32.f16.f16.f32 "
        "{%0,%1,%2,%3}, {%4,%5,%6,%7}, {%8,%9}, {%0,%1,%2,%3};"
        : "+f"(d[0]), "+f"(d[1]), "+f"(d[2]), "+f"(d[3])
        : "r"(a[0]), "r"(a[1]), "r"(a[2]), "r"(a[3]), "r"(b0), "r"(b1));
}

// ---------------- prep (merged): softmax+sel frags | resp frags + thr/invT ----------------
__global__ void prep_all(const float* __restrict__ fl, const float* __restrict__ resp,
                         const float* __restrict__ th, const float* __restrict__ lt) {
    const int tid = threadIdx.x;
    if (blockIdx.x < NTD) {
        __shared__ float red[8];
        __shared__ float sval[NF];
        const int td = blockIdx.x;

        float v = fl[tid * NTD + td];
        float m = v;
        #pragma unroll
        for (int o = 16; o; o >>= 1) m = fmaxf(m, __shfl_xor_sync(0xffffffffu, m, o));
        if ((tid & 31) == 0) red[tid >> 5] = m;
        __syncthreads();
        float bm = red[0];
        #pragma unroll
        for (int k = 1; k < 8; k++) bm = fmaxf(bm, red[k]);
        __syncthreads();
        float e = __expf(v - bm);
        float s = e;
        #pragma unroll
        for (int o = 16; o; o >>= 1) s += __shfl_xor_sync(0xffffffffu, s, o);
        if ((tid & 31) == 0) red[tid >> 5] = s;
        __syncthreads();
        float bs = 0.0f;
        #pragma unroll
        for (int k = 0; k < 8; k++) bs += red[k];
        sval[tid] = e / bs;
        __syncthreads();

        if (tid < 64) {
            int kc = tid >> 4, kk = (tid >> 2) & 3, fq = tid & 3;
            int h = td / 192, r = td % 192;
            int wn = r / 48, r2 = r % 48;
            int nt = r2 / 8, lr = r2 % 8;
            int lane = lr * 4 + fq;
            int f0 = kc * 64 + kk * 16 + fq * 2;
            uint32_t h0 = cvt2h(sval[f0],     sval[f0 + 1]);
            uint32_t h1 = cvt2h(sval[f0 + 8], sval[f0 + 9]);
            int j = ((((h * 4 + kc) * 4 + wn) * 6 + nt) * 4 + kk) * 32 + lane;
            g_sf[j] = make_uint2(h0, h1);
        }
    } else {
        int i = (blockIdx.x - NTD) * 256 + tid;    // < 262144 uint32
        if (i < NTD) g_thrT[i] = make_float2(th[i], __expf(-lt[i]));
        int fi   = i & 3;
        int lane = (i >> 2) & 31;
        int q    = (i >> 7) & 7;
        int wn   = (i >> 10) & 3;
        int t    = i >> 12;
        int m    = q * 4 + fi;
        int slot = m >> 1, reg = m & 1;
        int kk   = slot >> 2, nt = slot & 3;
        int n    = wn * 32 + nt * 8 + (lane >> 2);
        int k    = kk * 16 + (lane & 3) * 2 + reg * 8;
        const float* rb = resp + t * (NU * NLEAF) + n * NLEAF + k;
        const float sc = 1.0f / 64.0f;
        ((uint32_t*)g_rf)[i] = cvt2h(rb[0] * sc, rb[1] * sc);
    }
}

// ---------------- main fused kernel: 512 threads, 4x4 warp grid ----------------
__global__ __launch_bounds__(NTHR, 1) void odt_main(
    const float* __restrict__ x, float* __restrict__ out)
{
    extern __shared__ float smem[];
    char* smemc = (char*)smem;
    float* sp = smem + SP_FLOAT;

    const int tid = threadIdx.x;
    const int wid = tid >> 5;
    const int lid = tid & 31;
    const int s0  = blockIdx.x * TS;
    const uint32_t smem_base = smem_u32(smem);

    // 4x4 warp tiling (both phases): warp (wm, wn)
    const int wm = wid >> 2, wn = wid & 3;
    const uint32_t swz = (lid & 7) * 16;
    uint32_t xa[4];
    #pragma unroll
    for (int kk = 0; kk < 4; ++kk)
        xa[kk] = ((uint32_t)(kk * 32) + ((lid >> 4) * 16)) ^ swz;
    const uint32_t aRowOff = (wm * 32 + (lid & 15)) * 128;

    // ---- load x ONCE: [128 s][256 f] fp32 -> fp16 swizzled resident tile ----
    #pragma unroll
    for (int it = 0; it < 16; ++it) {
        int idx = tid + it * NTHR;         // 8192 float4
        int chunk = idx >> 11;
        int r = idx & 2047;
        int row = r >> 4, c4 = r & 15;
        float4 v = *(const float4*)(x + (s0 + row) * NF + chunk * 64 + c4 * 4);
        char* dh = smemc + chunk * 16384;
        int base = row * 128;
        int sz = (row & 7) * 16;
        *(uint32_t*)(dh + base + ((c4 * 8) ^ sz))     = cvt2h(v.x, v.y);
        *(uint32_t*)(dh + base + ((c4 * 8 + 4) ^ sz)) = cvt2h(v.z, v.w);
    }
    __syncthreads();

    float acc[2][4][4];                    // phase C accumulators (persist)
    #pragma unroll
    for (int m = 0; m < 2; m++)
        #pragma unroll
        for (int i = 0; i < 4; i++)
            #pragma unroll
            for (int j = 0; j < 4; j++) acc[m][i][j] = 0.0f;

    for (int half = 0; half < 2; ++half) {
        // ---------------- Phase B: fv via single-pass fp16 HMMA (no syncs) ----------------
        float accB[2][6][4];
        #pragma unroll
        for (int m = 0; m < 2; m++)
            #pragma unroll
            for (int i = 0; i < 6; i++)
                #pragma unroll
                for (int j = 0; j < 4; j++) accB[m][i][j] = 0.0f;

        for (int kc = 0; kc < 4; ++kc) {
            const uint32_t xhb = smem_base + kc * 16384;
            const uint2* bp = g_sf + ((size_t)(((half * 4 + kc) * 4 + wn) * 6) * 4) * 32 + lid;
            #pragma unroll
            for (int kk = 0; kk < 4; ++kk) {
                uint2 bq[6];
                #pragma unroll
                for (int nt = 0; nt < 6; ++nt) bq[nt] = bp[(nt * 4 + kk) * 32];
                #pragma unroll
                for (int mt = 0; mt < 2; ++mt) {
                    uint32_t ah[4];
                    ldsm4(ah, xhb + aRowOff + mt * 2048 + xa[kk]);
                    #pragma unroll
                    for (int nt = 0; nt < 6; ++nt)
                        mma16816(accB[mt][nt], ah, bq[nt].x, bq[nt].y);
                }
            }
        }

        __syncthreads();   // prev phase C done reading sp before overwrite
        // sigmoid((fv - thr) * invT) -> sp[td_local][row-pair permuted]
        // rows r and r+8 of each 16-row block land in adjacent slots: slot = q*2 + rr
        #pragma unroll
        for (int nt = 0; nt < 6; ++nt) {
            int c0 = wn * 48 + nt * 8 + (lid & 3) * 2;     // td within half
            float4 tt = *(const float4*)&g_thrT[half * 192 + c0];
            #pragma unroll
            for (int mt = 0; mt < 2; ++mt) {
                #pragma unroll
                for (int rr = 0; rr < 2; ++rr) {
                    int slot = wm * 32 + mt * 16 + (lid >> 2) * 2 + rr;
                    float t0 = (accB[mt][nt][rr * 2]     - tt.x) * tt.y;
                    float t1 = (accB[mt][nt][rr * 2 + 1] - tt.z) * tt.w;
                    sp[c0 * 128 + slot]       = __fdividef(1.0f, 1.0f + __expf(-t0));
                    sp[(c0 + 1) * 128 + slot] = __fdividef(1.0f, 1.0f + __expf(-t1));
                }
            }
        }
        __syncthreads();   // sp complete; phase C reads it

        // ---------------- Phase C: warp-independent fp16 HMMA (f16x2-packed A) ----------------
        for (int tt = 0; tt < 32; ++tt) {
            const int t = half * 32 + tt;

            uint4 bv[8];
            const uint4* bpc = g_rf + ((size_t)(t * 4 + wn) * 8) * 32 + lid;
            #pragma unroll
            for (int q = 0; q < 8; ++q) bv[q] = bpc[q * 32];
            const uint32_t* breg = (const uint32_t*)bv;

            const float* pbase = sp + tt * 6 * 128;

            #pragma unroll
            for (int mt = 0; mt < 2; ++mt) {
                // one LDS.64 per depth: {p[rr=0], p[rr=1]}
                const float2* pb = (const float2*)(pbase + wm * 32 + mt * 16) + (lid >> 2);
                float2 P0 = pb[0],   P1 = pb[64],  P2 = pb[128];
                float2 P3 = pb[192], P4 = pb[256], P5 = pb[320];

                uint32_t wl[2], mh[2][8];
                #pragma unroll
                for (int rr = 0; rr < 2; ++rr) {
                    float p0 = rr ? P0.y : P0.x, p1 = rr ? P1.y : P1.x;
                    float p2 = rr ? P2.y : P2.x, p3 = rr ? P3.y : P3.x;
                    float p4 = rr ? P4.y : P4.x, p5 = rr ? P5.y : P5.x;
                    float a0 = 1.f - p0, a1 = 1.f - p1, a2 = 1.f - p2;
                    float a3 = 1.f - p3, a4 = 1.f - p4, a5 = 1.f - p5;
                    float f1 = (lid & 1) ? p1 : a1;
                    float f2 = (lid & 2) ? p2 : a2;
                    float f12 = f1 * f2;
                    wl[rr] = cvt2h(f12 * a0, f12 * p0);
                    float g0 = a3 * a4, g1 = p3 * a4, g2 = a3 * p4, g3 = p3 * p4;
                    float m0 = g0 * a5, m1 = g1 * a5, m2 = g2 * a5, m3 = g3 * a5;
                    float m4 = g0 * p5, m5 = g1 * p5, m6 = g2 * p5, m7 = g3 * p5;
                    mh[rr][0] = cvt2h(m0, m0); mh[rr][1] = cvt2h(m1, m1);
                    mh[rr][2] = cvt2h(m2, m2); mh[rr][3] = cvt2h(m3, m3);
                    mh[rr][4] = cvt2h(m4, m4); mh[rr][5] = cvt2h(m5, m5);
                    mh[rr][6] = cvt2h(m6, m6); mh[rr][7] = cvt2h(m7, m7);
                }
                #pragma unroll
                for (int kk = 0; kk < 4; ++kk) {
                    uint32_t a[4];
                    a[0] = hmul2(wl[0], mh[0][2 * kk]);
                    a[1] = hmul2(wl[1], mh[1][2 * kk]);
                    a[2] = hmul2(wl[0], mh[0][2 * kk + 1]);
                    a[3] = hmul2(wl[1], mh[1][2 * kk + 1]);
                    #pragma unroll
                    for (int nt = 0; nt < 4; ++nt) {
                        int m = (kk * 4 + nt) * 2;
                        mma16816(acc[mt][nt], a, breg[m], breg[m + 1]);
                    }
                }
            }
        }
    }

    // ---------------- epilogue: frags -> smem stage -> coalesced global ----------------
    __syncthreads();
    {
        #pragma unroll
        for (int mt = 0; mt < 2; ++mt) {
            int r0 = wm * 32 + mt * 16 + (lid >> 2);
            #pragma unroll
            for (int n8 = 0; n8 < 4; ++n8) {
                int n = wn * 32 + n8 * 8 + (lid & 3) * 2;
                sp[r0 * 132 + n]           = acc[mt][n8][0];
                sp[r0 * 132 + n + 1]       = acc[mt][n8][1];
                sp[(r0 + 8) * 132 + n]     = acc[mt][n8][2];
                sp[(r0 + 8) * 132 + n + 1] = acc[mt][n8][3];
            }
        }
    }
    __syncthreads();

    #pragma unroll
    for (int it = 0; it < 8; ++it) {
        int idx = tid + it * NTHR;
        int s = idx >> 5, u4 = idx & 31;
        float4 v = *(const float4*)(sp + s * 132 + u4 * 4);
        *(float4*)(out + (s0 + s) * NU + u4 * 4) = v;
    }
}

extern "C" void kernel_launch(void* const* d_in, const int* in_sizes, int n_in,
                              void* d_out, int out_size) {
    const float* x  = (const float*)d_in[0];  // [16,1024,256]
    const float* fl = (const float*)d_in[1];  // [256,64,6]
    const float* th = (const float*)d_in[2];  // [64,6]
    const float* lt = (const float*)d_in[3];  // [64,6]
    const float* rs = (const float*)d_in[4];  // [64,128,64]
    float* out      = (float*)d_out;          // [16,1024,128]

    cudaFuncSetAttribute(odt_main, cudaFuncAttributeMaxDynamicSharedMemorySize, SMEM_BYTES);

    prep_all<<<NTD + 1024, 256>>>(fl, rs, th, lt);
    odt_main<<<NBLK, NTHR, SMEM_BYTES>>>(x, out);
}

// round 17
// speedup vs baseline: 1.2322x; 1.0980x over previous
#include <cuda_runtime.h>
#include <cuda_bf16.h>
#include <cuda_fp16.h>
#include <cstdint>

#define NF 256
#define NT 64
#define NDEP 6
#define NTD 384
#define NLEAF 64
#define NU 128
#define NSAMP 16384
#define TS 128
#define NBLK (NSAMP / TS)
#define NTHR 512

// ---- smem map (bytes) ----
// X resident fp16 tile (4 chunks of 16KB): [0, 65536)
// sp (fp32 p-values / epilogue staging):   [65536, 163840)
#define SP_FLOAT 16384
#define SMEM_BYTES 163840

__device__ float2 g_thrT[NTD];            // {threshold, exp(-logT)} per td
// R pre-packed in m16n8k16 B-fragment order (verified R8), scaled by 1/64:
__device__ uint4 g_rf[NT * 4 * 8 * 32];
// sel fp16 B-fragments: j = ((((h*4+kc)*4+wn4)*6+nt)*4+kk)*32+lane ; uint2 = {reg0, reg1}
__device__ uint2 g_sf[2 * 4 * 4 * 6 * 4 * 32];

__device__ __forceinline__ uint32_t cvt2h(float lo, float hi) {
    uint32_t r; asm("cvt.rn.f16x2.f32 %0, %1, %2;" : "=r"(r) : "f"(hi), "f"(lo)); return r;
}
__device__ __forceinline__ uint32_t hmul2(uint32_t a, uint32_t b) {
    uint32_t r; asm("mul.rn.f16x2 %0, %1, %2;" : "=r"(r) : "r"(a), "r"(b)); return r;
}
__device__ __forceinline__ uint32_t smem_u32(const void* p) {
    uint32_t a;
    asm("{ .reg .u64 t; cvta.to.shared.u64 t, %1; cvt.u32.u64 %0, t; }" : "=r"(a) : "l"(p));
    return a;
}
__device__ __forceinline__ void ldsm4(uint32_t* r, uint32_t addr) {
    asm volatile("ldmatrix.sync.aligned.m8n8.x4.shared.b16 {%0,%1,%2,%3}, [%4];"
                 : "=r"(r[0]), "=r"(r[1]), "=r"(r[2]), "=r"(r[3]) : "r"(addr));
}
__device__ __forceinline__ void mma16816(float* d, const uint32_t* a, uint32_t b0, uint32_t b1) {
    asm volatile(
        "mma.sync.aligned.m16n8k16.row.col.f32.f16.f16.f32 "
        "{%0,%1,%2,%3}, {%4,%5,%6,%7}, {%8,%9}, {%0,%1,%2,%3};"
        : "+f"(d[0]), "+f"(d[1]), "+f"(d[2]), "+f"(d[3])
        : "r"(a[0]), "r"(a[1]), "r"(a[2]), "r"(a[3]), "r"(b0), "r"(b1));
}

// ---------------- prep (merged): softmax+sel frags | resp frags + thr/invT ----------------
__global__ void prep_all(const float* __restrict__ fl, const float* __restrict__ resp,
                         const float* __restrict__ th, const float* __restrict__ lt) {
    const int tid = threadIdx.x;
    if (blockIdx.x < NTD) {
        __shared__ float red[8];
        __shared__ float sval[NF];
        const int td = blockIdx.x;

        float v = fl[tid * NTD + td];
        float m = v;
        #pragma unroll
        for (int o = 16; o; o >>= 1) m = fmaxf(m, __shfl_xor_sync(0xffffffffu, m, o));
        if ((tid & 31) == 0) red[tid >> 5] = m;
        __syncthreads();
        float bm = red[0];
        #pragma unroll
        for (int k = 1; k < 8; k++) bm = fmaxf(bm, red[k]);
        __syncthreads();
        float e = __expf(v - bm);
        float s = e;
        #pragma unroll
        for (int o = 16; o; o >>= 1) s += __shfl_xor_sync(0xffffffffu, s, o);
        if ((tid & 31) == 0) red[tid >> 5] = s;
        __syncthreads();
        float bs = 0.0f;
        #pragma unroll
        for (int k = 0; k < 8; k++) bs += red[k];
        sval[tid] = e / bs;
        __syncthreads();

        if (tid < 64) {
            int kc = tid >> 4, kk = (tid >> 2) & 3, fq = tid & 3;
            int h = td / 192, r = td % 192;
            int wn4 = r / 48, r2 = r % 48;
            int nt = r2 / 8, lr = r2 % 8;
            int lane = lr * 4 + fq;
            int f0 = kc * 64 + kk * 16 + fq * 2;
            uint32_t h0 = cvt2h(sval[f0],     sval[f0 + 1]);
            uint32_t h1 = cvt2h(sval[f0 + 8], sval[f0 + 9]);
            int j = ((((h * 4 + kc) * 4 + wn4) * 6 + nt) * 4 + kk) * 32 + lane;
            g_sf[j] = make_uint2(h0, h1);
        }
    } else {
        int i = (blockIdx.x - NTD) * 256 + tid;    // < 262144 uint32
        if (i < NTD) g_thrT[i] = make_float2(th[i], __expf(-lt[i]));
        int fi   = i & 3;
        int lane = (i >> 2) & 31;
        int q    = (i >> 7) & 7;
        int wn4  = (i >> 10) & 3;
        int t    = i >> 12;
        int m    = q * 4 + fi;
        int slot = m >> 1, reg = m & 1;
        int kk   = slot >> 2, nt = slot & 3;
        int n    = wn4 * 32 + nt * 8 + (lane >> 2);
        int k    = kk * 16 + (lane & 3) * 2 + reg * 8;
        const float* rb = resp + t * (NU * NLEAF) + n * NLEAF + k;
        const float sc = 1.0f / 64.0f;
        ((uint32_t*)g_rf)[i] = cvt2h(rb[0] * sc, rb[1] * sc);
    }
}

// ---------------- main fused kernel: 512 threads, 8x2 warp grid ----------------
__global__ __launch_bounds__(NTHR, 1) void odt_main(
    const float* __restrict__ x, float* __restrict__ out)
{
    extern __shared__ float smem[];
    char* smemc = (char*)smem;
    float* sp = smem + SP_FLOAT;

    const int tid = threadIdx.x;
    const int wid = tid >> 5;
    const int lid = tid & 31;
    const int s0  = blockIdx.x * TS;
    const uint32_t smem_base = smem_u32(smem);

    // 8x2 warp tiling: warp (wm, wn) owns rows [wm*16,+16), cols [wn*64,+64)
    const int wm = wid >> 1, wn = wid & 1;
    const uint32_t swz = (lid & 7) * 16;
    uint32_t xa[4];
    #pragma unroll
    for (int kk = 0; kk < 4; ++kk)
        xa[kk] = ((uint32_t)(kk * 32) + ((lid >> 4) * 16)) ^ swz;
    const uint32_t aRowOff = (wm * 16 + (lid & 15)) * 128;

    // ---- load x ONCE: [128 s][256 f] fp32 -> fp16 swizzled resident tile ----
    #pragma unroll
    for (int it = 0; it < 16; ++it) {
        int idx = tid + it * NTHR;         // 8192 float4
        int chunk = idx >> 11;
        int r = idx & 2047;
        int row = r >> 4, c4 = r & 15;
        float4 v = *(const float4*)(x + (s0 + row) * NF + chunk * 64 + c4 * 4);
        char* dh = smemc + chunk * 16384;
        int base = row * 128;
        int sz = (row & 7) * 16;
        *(uint32_t*)(dh + base + ((c4 * 8) ^ sz))     = cvt2h(v.x, v.y);
        *(uint32_t*)(dh + base + ((c4 * 8 + 4) ^ sz)) = cvt2h(v.z, v.w);
    }
    __syncthreads();

    float acc[8][4];                       // phase C accumulators [ng*4+nt][frag]
    #pragma unroll
    for (int i = 0; i < 8; i++)
        #pragma unroll
        for (int j = 0; j < 4; j++) acc[i][j] = 0.0f;

    for (int half = 0; half < 2; ++half) {
        // ---------------- Phase B: fv via single-pass fp16 HMMA (no syncs) ----------------
        float accB[12][4];                 // [ntg*6+nt][frag]
        #pragma unroll
        for (int i = 0; i < 12; i++)
            #pragma unroll
            for (int j = 0; j < 4; j++) accB[i][j] = 0.0f;

        for (int kc = 0; kc < 4; ++kc) {
            const uint32_t xhb = smem_base + kc * 16384;
            #pragma unroll
            for (int kk = 0; kk < 4; ++kk) {
                uint2 bq[12];
                #pragma unroll
                for (int ntg = 0; ntg < 2; ++ntg) {
                    const uint2* bp = g_sf +
                        ((size_t)(((half * 4 + kc) * 4 + (wn * 2 + ntg)) * 6) * 4) * 32 + lid;
                    #pragma unroll
                    for (int nt = 0; nt < 6; ++nt) bq[ntg * 6 + nt] = bp[(nt * 4 + kk) * 32];
                }
                uint32_t ah[4];
                ldsm4(ah, xhb + aRowOff + xa[kk]);
                #pragma unroll
                for (int j = 0; j < 12; ++j)
                    mma16816(accB[j], ah, bq[j].x, bq[j].y);
            }
        }

        __syncthreads();   // prev phase C done reading sp before overwrite
        // sigmoid((fv - thr) * invT) -> sp[td_local][row-pair permuted]
        #pragma unroll
        for (int ntg = 0; ntg < 2; ++ntg) {
            #pragma unroll
            for (int nt = 0; nt < 6; ++nt) {
                int j = ntg * 6 + nt;
                int c0 = wn * 96 + ntg * 48 + nt * 8 + (lid & 3) * 2;   // td within half
                float4 tt = *(const float4*)&g_thrT[half * 192 + c0];
                #pragma unroll
                for (int rr = 0; rr < 2; ++rr) {
                    int slot = wm * 16 + (lid >> 2) * 2 + rr;
                    float t0 = (accB[j][rr * 2]     - tt.x) * tt.y;
                    float t1 = (accB[j][rr * 2 + 1] - tt.z) * tt.w;
                    sp[c0 * 128 + slot]       = __fdividef(1.0f, 1.0f + __expf(-t0));
                    sp[(c0 + 1) * 128 + slot] = __fdividef(1.0f, 1.0f + __expf(-t1));
                }
            }
        }
        __syncthreads();   // sp complete; phase C reads it

        // ---------------- Phase C: fp16 HMMA, tables once per tree (1 row group) ----------------
        for (int tt = 0; tt < 32; ++tt) {
            const int t = half * 32 + tt;
            const uint4* bp0 = g_rf + ((size_t)(t * 4 + wn * 2) * 8) * 32 + lid;

            // B group ng=0 (cols wn*64 .. +32)
            uint4 bv0[8];
            #pragma unroll
            for (int q = 0; q < 8; ++q) bv0[q] = bp0[q * 32];

            // tables for this warp's 16 rows (one LDS.64 per depth)
            const float* pbase = sp + tt * 6 * 128;
            const float2* pb = (const float2*)(pbase + wm * 16) + (lid >> 2);
            float2 P0 = pb[0],   P1 = pb[64],  P2 = pb[128];
            float2 P3 = pb[192], P4 = pb[256], P5 = pb[320];

            uint32_t a[4][4];
            {
                uint32_t wl[2], mh[2][8];
                #pragma unroll
                for (int rr = 0; rr < 2; ++rr) {
                    float p0 = rr ? P0.y : P0.x, p1 = rr ? P1.y : P1.x;
                    float p2 = rr ? P2.y : P2.x, p3 = rr ? P3.y : P3.x;
                    float p4 = rr ? P4.y : P4.x, p5 = rr ? P5.y : P5.x;
                    float a0 = 1.f - p0, a1 = 1.f - p1, a2 = 1.f - p2;
                    float a3 = 1.f - p3, a4 = 1.f - p4, a5 = 1.f - p5;
                    float f1 = (lid & 1) ? p1 : a1;
                    float f2 = (lid & 2) ? p2 : a2;
                    float f12 = f1 * f2;
                    wl[rr] = cvt2h(f12 * a0, f12 * p0);
                    float g0 = a3 * a4, g1 = p3 * a4, g2 = a3 * p4, g3 = p3 * p4;
                    float m0 = g0 * a5, m1 = g1 * a5, m2 = g2 * a5, m3 = g3 * a5;
                    float m4 = g0 * p5, m5 = g1 * p5, m6 = g2 * p5, m7 = g3 * p5;
                    mh[rr][0] = cvt2h(m0, m0); mh[rr][1] = cvt2h(m1, m1);
                    mh[rr][2] = cvt2h(m2, m2); mh[rr][3] = cvt2h(m3, m3);
                    mh[rr][4] = cvt2h(m4, m4); mh[rr][5] = cvt2h(m5, m5);
                    mh[rr][6] = cvt2h(m6, m6); mh[rr][7] = cvt2h(m7, m7);
                }
                #pragma unroll
                for (int kk = 0; kk < 4; ++kk) {
                    a[kk][0] = hmul2(wl[0], mh[0][2 * kk]);
                    a[kk][1] = hmul2(wl[1], mh[1][2 * kk]);
                    a[kk][2] = hmul2(wl[0], mh[0][2 * kk + 1]);
                    a[kk][3] = hmul2(wl[1], mh[1][2 * kk + 1]);
                }
            }

            // B group ng=1 (cols wn*64+32 .. +32) — latency covered by ng=0 MMAs
            uint4 bv1[8];
            #pragma unroll
            for (int q = 0; q < 8; ++q) bv1[q] = bp0[256 + q * 32];

            const uint32_t* br0 = (const uint32_t*)bv0;
            #pragma unroll
            for (int kk = 0; kk < 4; ++kk) {
                #pragma unroll
                for (int nt = 0; nt < 4; ++nt) {
                    int m = (kk * 4 + nt) * 2;
                    mma16816(acc[nt], a[kk], br0[m], br0[m + 1]);
                }
            }
            const uint32_t* br1 = (const uint32_t*)bv1;
            #pragma unroll
            for (int kk = 0; kk < 4; ++kk) {
                #pragma unroll
                for (int nt = 0; nt < 4; ++nt) {
                    int m = (kk * 4 + nt) * 2;
                    mma16816(acc[4 + nt], a[kk], br1[m], br1[m + 1]);
                }
            }
        }
    }

    // ---------------- epilogue: frags -> smem stage -> coalesced global ----------------
    __syncthreads();
    {
        int r0 = wm * 16 + (lid >> 2);
        #pragma unroll
        for (int ng = 0; ng < 2; ++ng) {
            #pragma unroll
            for (int nt = 0; nt < 4; ++nt) {
                int n = wn * 64 + ng * 32 + nt * 8 + (lid & 3) * 2;
                sp[r0 * 132 + n]           = acc[ng * 4 + nt][0];
                sp[r0 * 132 + n + 1]       = acc[ng * 4 + nt][1];
                sp[(r0 + 8) * 132 + n]     = acc[ng * 4 + nt][2];
                sp[(r0 + 8) * 132 + n + 1] = acc[ng * 4 + nt][3];
            }
        }
    }
    __syncthreads();

    #pragma unroll
    for (int it = 0; it < 8; ++it) {
        int idx = tid + it * NTHR;
        int s = idx >> 5, u4 = idx & 31;
        float4 v = *(const float4*)(sp + s * 132 + u4 * 4);
        *(float4*)(out + (s0 + s) * NU + u4 * 4) = v;
    }
}

extern "C" void kernel_launch(void* const* d_in, const int* in_sizes, int n_in,
                              void* d_out, int out_size) {
    const float* x  = (const float*)d_in[0];  // [16,1024,256]
    const float* fl = (const float*)d_in[1];  // [256,64,6]
    const float* th = (const float*)d_in[2];  // [64,6]
    const float* lt = (const float*)d_in[3];  // [64,6]
    const float* rs = (const float*)d_in[4];  // [64,128,64]
    float* out      = (float*)d_out;          // [16,1024,128]

    cudaFuncSetAttribute(odt_main, cudaFuncAttributeMaxDynamicSharedMemorySize, SMEM_BYTES);

    prep_all<<<NTD + 1024, 256>>>(fl, rs, th, lt);
    odt_main<<<NBLK, NTHR, SMEM_BYTES>>>(x, out);
}